// round 14
// baseline (speedup 1.0000x reference)
#include <cuda_runtime.h>
#include <cuda_fp16.h>
#include <math.h>
#include <stdint.h>

#define BDIM 4096
#define DDIM 1024
#define KSEL 1024
#define EPSV 1e-6f
#define MARGINV 0.5f
#define FIXSCALE 1048576.0   // 2^20 fixed-point for deterministic atomic loss accum

// ---------------- scratch (device globals; allocation-free) ----------------
__device__ __half g_disth[(size_t)BDIM * BDIM];   // 32 MB
__device__ __half g_distTh[(size_t)BDIM * BDIM];  // 32 MB
__device__ float g_diag[BDIM];                    // fp32 diagonal (pos)
__device__ __half g_xh[(size_t)BDIM * DDIM];      // fp16-rounded X (8 MB)
__device__ __half g_yh[(size_t)BDIM * DDIM];      // fp16-rounded Y (8 MB)
__device__ float g_nx[BDIM];
__device__ float g_ny[BDIM];
__device__ float g_sy[BDIM];
__device__ unsigned long long g_acc[2];
__device__ unsigned g_done;

// ---------------- helpers ----------------
__device__ __forceinline__ uint32_t smem_u32(const void* p) {
    uint32_t a;
    asm("{ .reg .u64 t; cvta.to.shared.u64 t, %1; cvt.u32.u64 %0, t; }" : "=r"(a) : "l"(p));
    return a;
}
__device__ __forceinline__ void cp16(void* dst, const void* src) {
    uint32_t d = smem_u32(dst);
    asm volatile("cp.async.cg.shared.global [%0], [%1], 16;" :: "r"(d), "l"(src));
}
#define CP_COMMIT() asm volatile("cp.async.commit_group;")
#define CP_WAIT1()  asm volatile("cp.async.wait_group 1;")

__device__ __forceinline__ void mma_f16(float* c, const uint32_t* a, const uint32_t* b) {
    asm volatile(
        "mma.sync.aligned.m16n8k16.row.col.f32.f16.f16.f32 "
        "{%0,%1,%2,%3}, {%4,%5,%6,%7}, {%8,%9}, {%0,%1,%2,%3};"
        : "+f"(c[0]), "+f"(c[1]), "+f"(c[2]), "+f"(c[3])
        : "r"(a[0]), "r"(a[1]), "r"(a[2]), "r"(a[3]), "r"(b[0]), "r"(b[1]));
}

__device__ __forceinline__ void ldsm_x4(uint32_t& r0, uint32_t& r1, uint32_t& r2,
                                        uint32_t& r3, uint32_t addr) {
    asm volatile("ldmatrix.sync.aligned.m8n8.x4.shared.b16 {%0,%1,%2,%3}, [%4];"
                 : "=r"(r0), "=r"(r1), "=r"(r2), "=r"(r3) : "r"(addr));
}

__device__ __forceinline__ float pat2f(unsigned p) {
    return __half2float(__ushort_as_half((unsigned short)p));
}

// ---------------- GEMM config ----------------
#define BM 128
#define BN 128
#define BK 64
#define PITCHH 72
#define PITCHW 36
#define STAGE_BYTES (2 * 128 * PITCHH * 2)
#define NSTAGE 3
#define GEMM_SMEM (NSTAGE * STAGE_BYTES)

// ---------------------------------------------------------------------------
// Norms + fp16 pre-rounding (one float4 per thread); also resets accumulators
// ---------------------------------------------------------------------------
__global__ void __launch_bounds__(256) norms_kernel(const float* __restrict__ X,
                                                    const float* __restrict__ Y) {
    __shared__ float s1[256], s2[256];
    const int row = blockIdx.x;
    const int isY = blockIdx.y;
    const int tid = threadIdx.x;
    if (row == 0 && isY == 0 && tid == 0) {
        g_acc[0] = 0ull; g_acc[1] = 0ull; g_done = 0u;
    }
    const float4* p4 = (const float4*)((isY ? Y : X) + (size_t)row * DDIM);
    __half* ph = (isY ? g_yh : g_xh) + (size_t)row * DDIM;

    float4 v = p4[tid];
    __half2 h0 = __floats2half2_rn(v.x, v.y);
    __half2 h1 = __floats2half2_rn(v.z, v.w);
    uint2 u = make_uint2(*(const uint32_t*)&h0, *(const uint32_t*)&h1);
    *(uint2*)(ph + tid * 4) = u;

    float a, b = 0.0f;
    if (isY) {
        a = v.x * v.x + v.y * v.y + v.z * v.z + v.w * v.w;
        b = v.x + v.y + v.z + v.w;
    } else {
        float ex = v.x + EPSV, ey = v.y + EPSV, ez = v.z + EPSV, ew = v.w + EPSV;
        a = ex * ex + ey * ey + ez * ez + ew * ew;
    }
    s1[tid] = a; s2[tid] = b;
    __syncthreads();
    for (int off = 128; off; off >>= 1) {
        if (tid < off) { s1[tid] += s1[tid + off]; s2[tid] += s2[tid + off]; }
        __syncthreads();
    }
    if (tid == 0) {
        if (isY) { g_ny[row] = s1[0]; g_sy[row] = s2[0]; }
        else     { g_nx[row] = s1[0]; }
    }
}

// ---------------------------------------------------------------------------
// fp16 mma.sync GEMM with ldmatrix + distance epilogue  [identical to R12/13]
// ---------------------------------------------------------------------------
__device__ __forceinline__ void issue_stage(__half* sA, __half* sB,
                                            const __half* gA, const __half* gB, int tid) {
#pragma unroll
    for (int i = 0; i < 4; i++) {
        const int idx = tid + i * 256;
        const int r = idx >> 3;
        const int c = (idx & 7) * 8;
        cp16(sA + r * PITCHH + c, gA + (size_t)r * DDIM + c);
        cp16(sB + r * PITCHH + c, gB + (size_t)r * DDIM + c);
    }
}

__global__ void __launch_bounds__(256, 2) gemm_mma_kernel() {
    extern __shared__ __half smh[];
    const uint32_t sbase = smem_u32(smh);
    const int tid = threadIdx.x;
    const int wid = tid >> 5;
    const int lane = tid & 31;
    const int wm = wid & 3;
    const int wn = wid >> 2;
    const int g = lane >> 2;
    const int t = lane & 3;
    const int bi = blockIdx.y * BM;
    const int bj = blockIdx.x * BN;

    const __half* gA = g_xh + (size_t)bi * DDIM;
    const __half* gB = g_yh + (size_t)bj * DDIM;

    float acc[2][8][4];
#pragma unroll
    for (int mi = 0; mi < 2; mi++)
#pragma unroll
        for (int ni = 0; ni < 8; ni++)
#pragma unroll
            for (int e = 0; e < 4; e++) acc[mi][ni][e] = 0.0f;

    const int STAGE_H = 2 * 128 * PITCHH;
    const uint32_t B_OFF = 128 * PITCHH * 2;

    const int mrow = lane & 7;
    const int mm = lane >> 3;
    const uint32_t aOff = (uint32_t)(((wm * 32 + mrow + (mm & 1) * 8) * PITCHW
                                      + (mm >> 1) * 4) * 4);
    const uint32_t bOff = (uint32_t)(((wn * 64 + mrow + (mm >> 1) * 8) * PITCHW
                                      + (mm & 1) * 4) * 4);

    issue_stage(smh, smh + 128 * PITCHH, gA, gB, tid);
    CP_COMMIT();
    issue_stage(smh + STAGE_H, smh + STAGE_H + 128 * PITCHH,
                gA + BK, gB + BK, tid);
    CP_COMMIT();

    const int NCHUNK = DDIM / BK;
    for (int c = 0; c < NCHUNK; c++) {
        CP_WAIT1();
        __syncthreads();

        if (c + 2 < NCHUNK) {
            __half* nb = smh + ((c + 2) % NSTAGE) * STAGE_H;
            issue_stage(nb, nb + 128 * PITCHH,
                        gA + (c + 2) * BK, gB + (c + 2) * BK, tid);
        }
        CP_COMMIT();

        const uint32_t stg = sbase + (uint32_t)((c % NSTAGE) * STAGE_BYTES);
        const uint32_t aBase = stg + aOff;
        const uint32_t bBase = stg + B_OFF + bOff;

#pragma unroll
        for (int ks = 0; ks < 4; ks++) {
            const uint32_t kb = (uint32_t)(ks * 32);
            uint32_t a[2][4], b[8][2];
            ldsm_x4(a[0][0], a[0][1], a[0][2], a[0][3], aBase + kb);
            ldsm_x4(a[1][0], a[1][1], a[1][2], a[1][3],
                    aBase + kb + 16 * PITCHW * 4);
#pragma unroll
            for (int p = 0; p < 4; p++) {
                ldsm_x4(b[2 * p][0], b[2 * p][1], b[2 * p + 1][0], b[2 * p + 1][1],
                        bBase + kb + (uint32_t)(p * 16 * PITCHW * 4));
            }
#pragma unroll
            for (int mi = 0; mi < 2; mi++)
#pragma unroll
                for (int ni = 0; ni < 8; ni++)
                    mma_f16(acc[mi][ni], a[mi], b[ni]);
        }
    }

    __syncthreads();
    float* tile = (float*)smh;
    float* nx_s = tile + 128 * 129;
    float* ny_s = nx_s + 128;
    float* sy_s = ny_s + 128;
    if (tid < 128) {
        nx_s[tid] = g_nx[bi + tid];
        ny_s[tid] = g_ny[bj + tid];
        sy_s[tid] = g_sy[bj + tid];
    }
    __syncthreads();

#pragma unroll
    for (int mi = 0; mi < 2; mi++) {
        const int r0 = wm * 32 + mi * 16 + g;
#pragma unroll
        for (int ni = 0; ni < 8; ni++) {
            const int c0 = wn * 64 + ni * 8 + 2 * t;
#pragma unroll
            for (int e = 0; e < 4; e++) {
                const int row = r0 + (e >> 1) * 8;
                const int col = c0 + (e & 1);
                float sq = nx_s[row] + ny_s[col] - 2.0f * acc[mi][ni][e]
                           - 2.0f * EPSV * sy_s[col];
                tile[row * 129 + col] = sqrtf(fmaxf(sq, 0.0f));
            }
        }
    }
    __syncthreads();

    if (blockIdx.x == blockIdx.y && tid < 128)
        g_diag[bi + tid] = tile[tid * 129 + tid];

    for (int i = tid; i < 128 * 32; i += 256) {
        const int rr = i >> 5;
        const int c4 = (i & 31) << 2;
        const float* tp = &tile[rr * 129 + c4];
        __half2 h0 = __floats2half2_rn(tp[0], tp[1]);
        __half2 h1 = __floats2half2_rn(tp[2], tp[3]);
        uint2 u = make_uint2(*(const uint32_t*)&h0, *(const uint32_t*)&h1);
        *(uint2*)&g_disth[(size_t)(bi + rr) * BDIM + bj + c4] = u;
    }
    for (int i = tid; i < 128 * 128; i += 256) {
        const int rr = i & 127;
        const int cc = i >> 7;
        g_distTh[(size_t)(bj + cc) * BDIM + bi + rr] = __float2half(tile[rr * 129 + cc]);
    }
}

// ---------------------------------------------------------------------------
// Per-row loss, TWO rows per CTA (rows 2bx, 2bx+1 of one matrix), sharing all
// barriers. Packed u32 counts (__reduce_add_sync) and mins (__vminu2).
// Deterministic u64 fixed-point atomic accumulation; last CTA writes out[2].
// grid (BDIM/2, 2).
// ---------------------------------------------------------------------------
__global__ void __launch_bounds__(256) select_kernel(float* __restrict__ out) {
    __shared__ unsigned hist[512];
    __shared__ unsigned wuC[8];
    __shared__ float wfA[8], wfB[8];
    __shared__ unsigned wmn[8];
    __shared__ float s_tA, s_tB;
    __shared__ unsigned s_ct;        // packed counts (A low, B high)
    __shared__ float s_sallA, s_sallB;
    __shared__ unsigned s_mn;        // packed mins
    __shared__ unsigned s_cd;        // packed walk counts
    __shared__ unsigned s_thA, s_thB;

    const int rA = blockIdx.x * 2;
    const int rB = rA + 1;
    const int tid = threadIdx.x;
    const int wid = tid >> 5;
    const int lane = tid & 31;
    const __half* mat = blockIdx.y ? g_distTh : g_disth;

    const uint4* pA = (const uint4*)(mat + (size_t)rA * BDIM);
    const uint4* pB = (const uint4*)(mat + (size_t)rB * BDIM);

    unsigned rvA[8], rvB[8];
    {
        uint4 a0 = pA[tid], a1 = pA[tid + 256];
        uint4 b0 = pB[tid], b1 = pB[tid + 256];
        rvA[0] = a0.x; rvA[1] = a0.y; rvA[2] = a0.z; rvA[3] = a0.w;
        rvA[4] = a1.x; rvA[5] = a1.y; rvA[6] = a1.z; rvA[7] = a1.w;
        rvB[0] = b0.x; rvB[1] = b0.y; rvB[2] = b0.z; rvB[3] = b0.w;
        rvB[4] = b1.x; rvB[5] = b1.y; rvB[6] = b1.z; rvB[7] = b1.w;
    }

    if (tid == 0) { s_tA = MARGINV + g_diag[rA]; s_tB = MARGINV + g_diag[rB]; }

    // patch diagonals to +inf pattern (register-local)
    {
        const int uA = rA >> 3;
        if ((uA & 255) == tid) {
            const int w = ((uA >> 8) << 2) | ((rA >> 1) & 3);
            if (rA & 1) rvA[w] = (rvA[w] & 0x0000FFFFu) | 0x7C000000u;
            else        rvA[w] = (rvA[w] & 0xFFFF0000u) | 0x00007C00u;
        }
        const int uB = rB >> 3;
        if ((uB & 255) == tid) {
            const int w = ((uB >> 8) << 2) | ((rB >> 1) & 3);
            if (rB & 1) rvB[w] = (rvB[w] & 0x0000FFFFu) | 0x7C000000u;
            else        rvB[w] = (rvB[w] & 0xFFFF0000u) | 0x00007C00u;
        }
    }
    __syncthreads();
    const float tA = s_tA, tB = s_tB;

    unsigned tcA, tcB;
    {
        __half h = __float2half_rd(tA);
        tcA = (unsigned)__half_as_ushort(h) + (tA > __half2float(h) ? 1u : 0u);
        h = __float2half_rd(tB);
        tcB = (unsigned)__half_as_ushort(h) + (tB > __half2float(h) ? 1u : 0u);
    }

    // ---- fused sweep: counts & sums below t, mins (both rows) ----
    unsigned cA = 0, cB = 0, mnA = 0x7C00u, mnB = 0x7C00u;
    float sA = 0.0f, sB = 0.0f;
#pragma unroll
    for (int w = 0; w < 8; w++) {
        unsigned lo = rvA[w] & 0xFFFFu, hi = rvA[w] >> 16;
        if (lo < tcA) { cA++; sA += pat2f(lo); }
        if (hi < tcA) { cA++; sA += pat2f(hi); }
        mnA = min(mnA, min(lo, hi));
        lo = rvB[w] & 0xFFFFu; hi = rvB[w] >> 16;
        if (lo < tcB) { cB++; sB += pat2f(lo); }
        if (hi < tcB) { cB++; sB += pat2f(hi); }
        mnB = min(mnB, min(lo, hi));
    }
    unsigned cpk = __reduce_add_sync(0xFFFFFFFFu, cA | (cB << 16));
    unsigned mpk = mnA | (mnB << 16);
#pragma unroll
    for (int off = 16; off; off >>= 1) {
        mpk = __vminu2(mpk, __shfl_down_sync(0xFFFFFFFFu, mpk, off));
        sA += __shfl_down_sync(0xFFFFFFFFu, sA, off);
        sB += __shfl_down_sync(0xFFFFFFFFu, sB, off);
    }
    if (lane == 0) { wuC[wid] = cpk; wfA[wid] = sA; wfB[wid] = sB; wmn[wid] = mpk; }
    __syncthreads();
    if (tid == 0) {
        unsigned ct = 0, mt = 0x7C007C00u;
        float fa = 0.0f, fb = 0.0f;
#pragma unroll
        for (int w = 0; w < 8; w++) {
            ct += wuC[w]; fa += wfA[w]; fb += wfB[w]; mt = __vminu2(mt, wmn[w]);
        }
        s_ct = ct; s_sallA = fa; s_sallB = fb; s_mn = mt;
    }
    __syncthreads();
    const unsigned ctA = s_ct & 0xFFFFu, ctB = s_ct >> 16;
    const bool selA = ctA > KSEL, selB = ctB > KSEL;

    float rlA = (float)ctA * tA - s_sallA;   // valid when !selA
    float rlB = (float)ctB * tB - s_sallB;

    if (selA || selB) {
        // ---- top-byte digit walks (both rows, shared barriers) ----
        bool wkA = selA, wkB = selB;
        unsigned remkA = KSEL, remkB = KSEL;
        unsigned DA = (s_mn & 0xFFFFu) >> 8, DB = (s_mn >> 16) >> 8;
        while (wkA || wkB) {
            unsigned dA = 0, dB = 0;
            if (wkA)
#pragma unroll
                for (int w = 0; w < 8; w++) {
                    dA += (((rvA[w] & 0xFFFFu) >> 8) == DA);
                    dA += ((rvA[w] >> 24) == DA);
                }
            if (wkB)
#pragma unroll
                for (int w = 0; w < 8; w++) {
                    dB += (((rvB[w] & 0xFFFFu) >> 8) == DB);
                    dB += ((rvB[w] >> 24) == DB);
                }
            unsigned dpk = __reduce_add_sync(0xFFFFFFFFu, dA | (dB << 16));
            if (lane == 0) wuC[wid] = dpk;
            __syncthreads();
            if (tid == 0) {
                unsigned ct = 0;
#pragma unroll
                for (int w = 0; w < 8; w++) ct += wuC[w];
                s_cd = ct;
            }
            __syncthreads();
            const unsigned cdA = s_cd & 0xFFFFu, cdB = s_cd >> 16;
            __syncthreads();
            if (wkA) { if (cdA >= remkA) wkA = false; else { remkA -= cdA; DA++; } }
            if (wkB) { if (cdB >= remkB) wkB = false; else { remkB -= cdB; DB++; } }
        }

        // ---- low-byte histogram pass (both rows) ----
        hist[tid] = 0; hist[tid + 256] = 0;
        __syncthreads();
        if (selA)
#pragma unroll
            for (int w = 0; w < 8; w++) {
                const unsigned lo = rvA[w] & 0xFFFFu, hi = rvA[w] >> 16;
                if ((lo >> 8) == DA) atomicAdd(&hist[lo & 255u], 1u);
                if ((hi >> 8) == DA) atomicAdd(&hist[hi & 255u], 1u);
            }
        if (selB)
#pragma unroll
            for (int w = 0; w < 8; w++) {
                const unsigned lo = rvB[w] & 0xFFFFu, hi = rvB[w] >> 16;
                if ((lo >> 8) == DB) atomicAdd(&hist[256 + (lo & 255u)], 1u);
                if ((hi >> 8) == DB) atomicAdd(&hist[256 + (hi & 255u)], 1u);
            }
        __syncthreads();
        // warp 0 scans row A, warp 1 scans row B
        if ((wid == 0 && selA) || (wid == 1 && selB)) {
            const unsigned* hh = hist + wid * 256;
            const unsigned remk = wid ? remkB : remkA;
            const unsigned D = wid ? DB : DA;
            unsigned loc[8]; unsigned lsum = 0;
#pragma unroll
            for (int j = 0; j < 8; j++) { loc[j] = hh[lane * 8 + j]; lsum += loc[j]; }
            unsigned incl = lsum;
#pragma unroll
            for (int off = 1; off < 32; off <<= 1) {
                unsigned y = __shfl_up_sync(0xFFFFFFFFu, incl, off);
                if (lane >= off) incl += y;
            }
            const unsigned excl = incl - lsum;
            if (excl < remk && incl >= remk) {
                unsigned cum = excl;
#pragma unroll
                for (int j = 0; j < 8; j++) {
                    if (cum + loc[j] >= remk) {
                        if (wid) s_thB = (D << 8) | (unsigned)(lane * 8 + j);
                        else     s_thA = (D << 8) | (unsigned)(lane * 8 + j);
                        break;
                    }
                    cum += loc[j];
                }
            }
        }
        __syncthreads();

        // ---- final sweep: sum/count strictly below theta ----
        unsigned clA = 0, clB = 0;
        float slA = 0.0f, slB = 0.0f;
        const unsigned thA = s_thA, thB = s_thB;
        if (selA)
#pragma unroll
            for (int w = 0; w < 8; w++) {
                const unsigned lo = rvA[w] & 0xFFFFu, hi = rvA[w] >> 16;
                if (lo < thA) { clA++; slA += pat2f(lo); }
                if (hi < thA) { clA++; slA += pat2f(hi); }
            }
        if (selB)
#pragma unroll
            for (int w = 0; w < 8; w++) {
                const unsigned lo = rvB[w] & 0xFFFFu, hi = rvB[w] >> 16;
                if (lo < thB) { clB++; slB += pat2f(lo); }
                if (hi < thB) { clB++; slB += pat2f(hi); }
            }
        unsigned clpk = __reduce_add_sync(0xFFFFFFFFu, clA | (clB << 16));
#pragma unroll
        for (int off = 16; off; off >>= 1) {
            slA += __shfl_down_sync(0xFFFFFFFFu, slA, off);
            slB += __shfl_down_sync(0xFFFFFFFFu, slB, off);
        }
        if (lane == 0) { wuC[wid] = clpk; wfA[wid] = slA; wfB[wid] = slB; }
        __syncthreads();
        if (tid == 0) {
            unsigned ct = 0; float fa = 0.0f, fb = 0.0f;
#pragma unroll
            for (int w = 0; w < 8; w++) { ct += wuC[w]; fa += wfA[w]; fb += wfB[w]; }
            if (selA) {
                const float thf = pat2f(s_thA);
                rlA = (float)KSEL * tA - fa - (float)(KSEL - (ct & 0xFFFFu)) * thf;
            }
            if (selB) {
                const float thf = pat2f(s_thB);
                rlB = (float)KSEL * tB - fb - (float)(KSEL - (ct >> 16)) * thf;
            }
        }
    }

    // ---- deterministic fixed-point accumulation; last CTA finalizes ----
    if (tid == 0) {
        const unsigned long long fx =
            (unsigned long long)((double)(rlA + rlB) * FIXSCALE);
        atomicAdd(&g_acc[blockIdx.y], fx);
        __threadfence();
        const unsigned done = atomicAdd(&g_done, 1u);
        if (done == (unsigned)(BDIM / 2) * 2u - 1u) {
            const unsigned long long a0 = atomicAdd(&g_acc[0], 0ull);
            const unsigned long long a1 = atomicAdd(&g_acc[1], 0ull);
            const double denom = FIXSCALE * (double)BDIM * (double)KSEL;
            out[0] = (float)((double)a0 / denom);
            out[1] = (float)((double)a1 / denom);
        }
    }
}

// ---------------------------------------------------------------------------
extern "C" void kernel_launch(void* const* d_in, const int* in_sizes, int n_in,
                              void* d_out, int out_size) {
    const float* X = (const float*)d_in[0];
    const float* Y = (const float*)d_in[1];
    float* out = (float*)d_out;

    cudaFuncSetAttribute(gemm_mma_kernel, cudaFuncAttributeMaxDynamicSharedMemorySize,
                         GEMM_SMEM);

    norms_kernel<<<dim3(BDIM, 2), 256>>>(X, Y);
    gemm_mma_kernel<<<dim3(BDIM / BN, BDIM / BM), 256, GEMM_SMEM>>>();
    select_kernel<<<dim3(BDIM / 2, 2), 256>>>(out);
}

// round 15
// speedup vs baseline: 1.0200x; 1.0200x over previous
#include <cuda_runtime.h>
#include <cuda_fp16.h>
#include <math.h>
#include <stdint.h>

#define BDIM 4096
#define DDIM 1024
#define KSEL 1024
#define EPSV 1e-6f
#define MARGINV 0.5f
#define FIXSCALE 1048576.0   // 2^20 fixed-point for deterministic atomic loss accum

// ---------------- scratch (device globals; allocation-free) ----------------
__device__ __half g_disth[(size_t)BDIM * BDIM];   // 32 MB
__device__ __half g_distTh[(size_t)BDIM * BDIM];  // 32 MB
__device__ float g_diag[BDIM];                    // fp32 diagonal (pos)
__device__ __half g_xh[(size_t)BDIM * DDIM];      // fp16-rounded X (8 MB)
__device__ __half g_yh[(size_t)BDIM * DDIM];      // fp16-rounded Y (8 MB)
__device__ float g_nx[BDIM];
__device__ float g_ny[BDIM];
__device__ float g_sy[BDIM];
__device__ unsigned long long g_acc[2];
__device__ unsigned g_done;

// ---------------- helpers ----------------
__device__ __forceinline__ uint32_t smem_u32(const void* p) {
    uint32_t a;
    asm("{ .reg .u64 t; cvta.to.shared.u64 t, %1; cvt.u32.u64 %0, t; }" : "=r"(a) : "l"(p));
    return a;
}
__device__ __forceinline__ void cp16(void* dst, const void* src) {
    uint32_t d = smem_u32(dst);
    asm volatile("cp.async.cg.shared.global [%0], [%1], 16;" :: "r"(d), "l"(src));
}
#define CP_COMMIT() asm volatile("cp.async.commit_group;")
#define CP_WAIT1()  asm volatile("cp.async.wait_group 1;")

__device__ __forceinline__ void mma_f16(float* c, const uint32_t* a, const uint32_t* b) {
    asm volatile(
        "mma.sync.aligned.m16n8k16.row.col.f32.f16.f16.f32 "
        "{%0,%1,%2,%3}, {%4,%5,%6,%7}, {%8,%9}, {%0,%1,%2,%3};"
        : "+f"(c[0]), "+f"(c[1]), "+f"(c[2]), "+f"(c[3])
        : "r"(a[0]), "r"(a[1]), "r"(a[2]), "r"(a[3]), "r"(b[0]), "r"(b[1]));
}

__device__ __forceinline__ void ldsm_x4(uint32_t& r0, uint32_t& r1, uint32_t& r2,
                                        uint32_t& r3, uint32_t addr) {
    asm volatile("ldmatrix.sync.aligned.m8n8.x4.shared.b16 {%0,%1,%2,%3}, [%4];"
                 : "=r"(r0), "=r"(r1), "=r"(r2), "=r"(r3) : "r"(addr));
}

__device__ __forceinline__ float pat2f(unsigned p) {
    return __half2float(__ushort_as_half((unsigned short)p));
}

// ---------------- GEMM config ----------------
#define BM 128
#define BN 128
#define BK 64
#define PITCHH 72
#define PITCHW 36
#define STAGE_BYTES (2 * 128 * PITCHH * 2)
#define NSTAGE 3
#define GEMM_SMEM (NSTAGE * STAGE_BYTES)

// ---------------------------------------------------------------------------
// Norms + fp16 pre-rounding (one float4 per thread), shuffle reductions.
// Also resets the loss accumulators (block (0,0)).
// ---------------------------------------------------------------------------
__global__ void __launch_bounds__(256) norms_kernel(const float* __restrict__ X,
                                                    const float* __restrict__ Y) {
    __shared__ float w1[8], w2[8];
    const int row = blockIdx.x;
    const int isY = blockIdx.y;
    const int tid = threadIdx.x;
    const int wid = tid >> 5;
    const int lane = tid & 31;
    if (row == 0 && isY == 0 && tid == 0) {
        g_acc[0] = 0ull; g_acc[1] = 0ull; g_done = 0u;
    }
    const float4* p4 = (const float4*)((isY ? Y : X) + (size_t)row * DDIM);
    __half* ph = (isY ? g_yh : g_xh) + (size_t)row * DDIM;

    float4 v = p4[tid];
    __half2 h0 = __floats2half2_rn(v.x, v.y);
    __half2 h1 = __floats2half2_rn(v.z, v.w);
    uint2 u = make_uint2(*(const uint32_t*)&h0, *(const uint32_t*)&h1);
    *(uint2*)(ph + tid * 4) = u;

    float a, b = 0.0f;
    if (isY) {
        a = v.x * v.x + v.y * v.y + v.z * v.z + v.w * v.w;
        b = v.x + v.y + v.z + v.w;
    } else {
        float ex = v.x + EPSV, ey = v.y + EPSV, ez = v.z + EPSV, ew = v.w + EPSV;
        a = ex * ex + ey * ey + ez * ez + ew * ew;
    }
#pragma unroll
    for (int off = 16; off; off >>= 1) {
        a += __shfl_down_sync(0xFFFFFFFFu, a, off);
        b += __shfl_down_sync(0xFFFFFFFFu, b, off);
    }
    if (lane == 0) { w1[wid] = a; w2[wid] = b; }
    __syncthreads();
    if (wid == 0) {
        float aa = (lane < 8) ? w1[lane] : 0.0f;
        float bb = (lane < 8) ? w2[lane] : 0.0f;
#pragma unroll
        for (int off = 4; off; off >>= 1) {
            aa += __shfl_down_sync(0xFFFFFFFFu, aa, off);
            bb += __shfl_down_sync(0xFFFFFFFFu, bb, off);
        }
        if (lane == 0) {
            if (isY) { g_ny[row] = aa; g_sy[row] = bb; }
            else     { g_nx[row] = aa; }
        }
    }
}

// ---------------------------------------------------------------------------
// fp16 mma.sync GEMM with ldmatrix + distance epilogue  [identical to R12/13]
// ---------------------------------------------------------------------------
__device__ __forceinline__ void issue_stage(__half* sA, __half* sB,
                                            const __half* gA, const __half* gB, int tid) {
#pragma unroll
    for (int i = 0; i < 4; i++) {
        const int idx = tid + i * 256;
        const int r = idx >> 3;
        const int c = (idx & 7) * 8;
        cp16(sA + r * PITCHH + c, gA + (size_t)r * DDIM + c);
        cp16(sB + r * PITCHH + c, gB + (size_t)r * DDIM + c);
    }
}

__global__ void __launch_bounds__(256, 2) gemm_mma_kernel() {
    extern __shared__ __half smh[];
    const uint32_t sbase = smem_u32(smh);
    const int tid = threadIdx.x;
    const int wid = tid >> 5;
    const int lane = tid & 31;
    const int wm = wid & 3;
    const int wn = wid >> 2;
    const int g = lane >> 2;
    const int t = lane & 3;
    const int bi = blockIdx.y * BM;
    const int bj = blockIdx.x * BN;

    const __half* gA = g_xh + (size_t)bi * DDIM;
    const __half* gB = g_yh + (size_t)bj * DDIM;

    float acc[2][8][4];
#pragma unroll
    for (int mi = 0; mi < 2; mi++)
#pragma unroll
        for (int ni = 0; ni < 8; ni++)
#pragma unroll
            for (int e = 0; e < 4; e++) acc[mi][ni][e] = 0.0f;

    const int STAGE_H = 2 * 128 * PITCHH;
    const uint32_t B_OFF = 128 * PITCHH * 2;

    const int mrow = lane & 7;
    const int mm = lane >> 3;
    const uint32_t aOff = (uint32_t)(((wm * 32 + mrow + (mm & 1) * 8) * PITCHW
                                      + (mm >> 1) * 4) * 4);
    const uint32_t bOff = (uint32_t)(((wn * 64 + mrow + (mm >> 1) * 8) * PITCHW
                                      + (mm & 1) * 4) * 4);

    issue_stage(smh, smh + 128 * PITCHH, gA, gB, tid);
    CP_COMMIT();
    issue_stage(smh + STAGE_H, smh + STAGE_H + 128 * PITCHH,
                gA + BK, gB + BK, tid);
    CP_COMMIT();

    const int NCHUNK = DDIM / BK;
    for (int c = 0; c < NCHUNK; c++) {
        CP_WAIT1();
        __syncthreads();

        if (c + 2 < NCHUNK) {
            __half* nb = smh + ((c + 2) % NSTAGE) * STAGE_H;
            issue_stage(nb, nb + 128 * PITCHH,
                        gA + (c + 2) * BK, gB + (c + 2) * BK, tid);
        }
        CP_COMMIT();

        const uint32_t stg = sbase + (uint32_t)((c % NSTAGE) * STAGE_BYTES);
        const uint32_t aBase = stg + aOff;
        const uint32_t bBase = stg + B_OFF + bOff;

#pragma unroll
        for (int ks = 0; ks < 4; ks++) {
            const uint32_t kb = (uint32_t)(ks * 32);
            uint32_t a[2][4], b[8][2];
            ldsm_x4(a[0][0], a[0][1], a[0][2], a[0][3], aBase + kb);
            ldsm_x4(a[1][0], a[1][1], a[1][2], a[1][3],
                    aBase + kb + 16 * PITCHW * 4);
#pragma unroll
            for (int p = 0; p < 4; p++) {
                ldsm_x4(b[2 * p][0], b[2 * p][1], b[2 * p + 1][0], b[2 * p + 1][1],
                        bBase + kb + (uint32_t)(p * 16 * PITCHW * 4));
            }
#pragma unroll
            for (int mi = 0; mi < 2; mi++)
#pragma unroll
                for (int ni = 0; ni < 8; ni++)
                    mma_f16(acc[mi][ni], a[mi], b[ni]);
        }
    }

    __syncthreads();
    float* tile = (float*)smh;
    float* nx_s = tile + 128 * 129;
    float* ny_s = nx_s + 128;
    float* sy_s = ny_s + 128;
    if (tid < 128) {
        nx_s[tid] = g_nx[bi + tid];
        ny_s[tid] = g_ny[bj + tid];
        sy_s[tid] = g_sy[bj + tid];
    }
    __syncthreads();

#pragma unroll
    for (int mi = 0; mi < 2; mi++) {
        const int r0 = wm * 32 + mi * 16 + g;
#pragma unroll
        for (int ni = 0; ni < 8; ni++) {
            const int c0 = wn * 64 + ni * 8 + 2 * t;
#pragma unroll
            for (int e = 0; e < 4; e++) {
                const int row = r0 + (e >> 1) * 8;
                const int col = c0 + (e & 1);
                float sq = nx_s[row] + ny_s[col] - 2.0f * acc[mi][ni][e]
                           - 2.0f * EPSV * sy_s[col];
                tile[row * 129 + col] = sqrtf(fmaxf(sq, 0.0f));
            }
        }
    }
    __syncthreads();

    if (blockIdx.x == blockIdx.y && tid < 128)
        g_diag[bi + tid] = tile[tid * 129 + tid];

    for (int i = tid; i < 128 * 32; i += 256) {
        const int rr = i >> 5;
        const int c4 = (i & 31) << 2;
        const float* tp = &tile[rr * 129 + c4];
        __half2 h0 = __floats2half2_rn(tp[0], tp[1]);
        __half2 h1 = __floats2half2_rn(tp[2], tp[3]);
        uint2 u = make_uint2(*(const uint32_t*)&h0, *(const uint32_t*)&h1);
        *(uint2*)&g_disth[(size_t)(bi + rr) * BDIM + bj + c4] = u;
    }
    for (int i = tid; i < 128 * 128; i += 256) {
        const int rr = i & 127;
        const int cc = i >> 7;
        g_distTh[(size_t)(bj + cc) * BDIM + bi + rr] = __float2half(tile[rr * 129 + cc]);
    }
}

// ---------------------------------------------------------------------------
// Per-row loss on fp16 distances (R13 body: 1 row/CTA, pattern-only regs,
// integer compares, digit walk + one histogram pass). Tail: deterministic
// u64 fixed-point atomic accumulation; last CTA writes out[2].
// grid (BDIM, 2).
// ---------------------------------------------------------------------------
__global__ void __launch_bounds__(256) select_kernel(float* __restrict__ out) {
    __shared__ unsigned hist[256];
    __shared__ float wf[8];
    __shared__ unsigned wu[8];
    __shared__ float s_t;
    __shared__ unsigned s_ctot;
    __shared__ float s_sall;
    __shared__ unsigned s_minp;
    __shared__ unsigned s_cd;
    __shared__ unsigned s_theta;
    __shared__ float s_rl;

    const int row = blockIdx.x;
    const int tid = threadIdx.x;
    const int wid = tid >> 5;
    const int lane = tid & 31;
    const __half* mat = blockIdx.y ? g_distTh : g_disth;
    const uint4* rp4 = (const uint4*)(mat + (size_t)row * BDIM);

    unsigned rv[8];
    {
        uint4 u0 = rp4[tid];
        uint4 u1 = rp4[tid + 256];
        rv[0] = u0.x; rv[1] = u0.y; rv[2] = u0.z; rv[3] = u0.w;
        rv[4] = u1.x; rv[5] = u1.y; rv[6] = u1.z; rv[7] = u1.w;
    }

    if (tid == 0) s_t = MARGINV + g_diag[row];

    {
        const int u4i = row >> 3;
        if ((u4i & 255) == tid) {
            const int w = ((u4i >> 8) << 2) | ((row >> 1) & 3);
            if (row & 1) rv[w] = (rv[w] & 0x0000FFFFu) | 0x7C000000u;
            else         rv[w] = (rv[w] & 0xFFFF0000u) | 0x00007C00u;
        }
    }
    __syncthreads();
    const float t = s_t;

    unsigned tcmp;
    {
        const __half thd = __float2half_rd(t);
        tcmp = (unsigned)__half_as_ushort(thd) + (t > __half2float(thd) ? 1u : 0u);
    }

    // ---- fused sweep: count & sum of v below t, min pattern ----
    unsigned c = 0; float s = 0.0f; unsigned mnp = 0x7C00u;
#pragma unroll
    for (int w = 0; w < 8; w++) {
        const unsigned lo = rv[w] & 0xFFFFu;
        const unsigned hi = rv[w] >> 16;
        if (lo < tcmp) { c++; s += pat2f(lo); }
        if (hi < tcmp) { c++; s += pat2f(hi); }
        mnp = min(mnp, min(lo, hi));
    }
    c = __reduce_add_sync(0xFFFFFFFFu, c);
    mnp = __reduce_min_sync(0xFFFFFFFFu, mnp);
#pragma unroll
    for (int off = 16; off; off >>= 1)
        s += __shfl_down_sync(0xFFFFFFFFu, s, off);
    if (lane == 0) { wu[wid] = c; wf[wid] = s; hist[wid] = mnp; }
    __syncthreads();
    if (tid == 0) {
        unsigned ct = 0; float st = 0.0f; unsigned mt = 0x7C00u;
#pragma unroll
        for (int w = 0; w < 8; w++) { ct += wu[w]; st += wf[w]; mt = min(mt, hist[w]); }
        s_ctot = ct; s_sall = st; s_minp = mt;
    }
    __syncthreads();

    if (s_ctot <= KSEL) {
        if (tid == 0) s_rl = (float)s_ctot * t - s_sall;
    } else {
        // ---- top-byte digit walk (atomic-free, integer) ----
        unsigned remk = KSEL;
        unsigned D = s_minp >> 8;
        for (;;) {
            unsigned cd = 0;
#pragma unroll
            for (int w = 0; w < 8; w++) {
                cd += (((rv[w] & 0xFFFFu) >> 8) == D);
                cd += ((rv[w] >> 24) == D);
            }
            cd = __reduce_add_sync(0xFFFFFFFFu, cd);
            if (lane == 0) wu[wid] = cd;
            __syncthreads();
            if (tid == 0) {
                unsigned ct = 0;
#pragma unroll
                for (int w = 0; w < 8; w++) ct += wu[w];
                s_cd = ct;
            }
            __syncthreads();
            const unsigned cdtot = s_cd;
            __syncthreads();
            if (cdtot >= remk) break;
            remk -= cdtot;
            D++;
        }

        // ---- single low-byte histogram pass ----
        hist[tid] = 0;
        __syncthreads();
#pragma unroll
        for (int w = 0; w < 8; w++) {
            const unsigned lo = rv[w] & 0xFFFFu;
            const unsigned hi = rv[w] >> 16;
            if ((lo >> 8) == D) atomicAdd(&hist[lo & 255u], 1u);
            if ((hi >> 8) == D) atomicAdd(&hist[hi & 255u], 1u);
        }
        __syncthreads();
        if (tid < 32) {
            unsigned loc[8]; unsigned lsum = 0;
#pragma unroll
            for (int j = 0; j < 8; j++) { loc[j] = hist[tid * 8 + j]; lsum += loc[j]; }
            unsigned incl = lsum;
#pragma unroll
            for (int off = 1; off < 32; off <<= 1) {
                unsigned y = __shfl_up_sync(0xFFFFFFFFu, incl, off);
                if (tid >= off) incl += y;
            }
            const unsigned excl = incl - lsum;
            if (excl < remk && incl >= remk) {
                unsigned cum = excl;
#pragma unroll
                for (int j = 0; j < 8; j++) {
                    if (cum + loc[j] >= remk) {
                        s_theta = (D << 8) | (unsigned)(tid * 8 + j);
                        break;
                    }
                    cum += loc[j];
                }
            }
        }
        __syncthreads();
        const unsigned theta_pat = s_theta;
        const float theta = pat2f(theta_pat);

        // ---- final: sum/count strictly below theta ----
        unsigned cl = 0; float sl = 0.0f;
#pragma unroll
        for (int w = 0; w < 8; w++) {
            const unsigned lo = rv[w] & 0xFFFFu;
            const unsigned hi = rv[w] >> 16;
            if (lo < theta_pat) { cl++; sl += pat2f(lo); }
            if (hi < theta_pat) { cl++; sl += pat2f(hi); }
        }
        cl = __reduce_add_sync(0xFFFFFFFFu, cl);
#pragma unroll
        for (int off = 16; off; off >>= 1)
            sl += __shfl_down_sync(0xFFFFFFFFu, sl, off);
        if (lane == 0) { wu[wid] = cl; wf[wid] = sl; }
        __syncthreads();
        if (tid == 0) {
            unsigned ct = 0; float st = 0.0f;
#pragma unroll
            for (int w = 0; w < 8; w++) { ct += wu[w]; st += wf[w]; }
            s_rl = (float)KSEL * t - st - (float)(KSEL - ct) * theta;
        }
    }
    __syncthreads();

    // ---- deterministic fixed-point accumulation; last CTA finalizes ----
    if (tid == 0) {
        const unsigned long long fx =
            (unsigned long long)((double)s_rl * FIXSCALE);
        atomicAdd(&g_acc[blockIdx.y], fx);
        __threadfence();
        const unsigned done = atomicAdd(&g_done, 1u);
        if (done == (unsigned)BDIM * 2u - 1u) {
            const unsigned long long a0 = atomicAdd(&g_acc[0], 0ull);
            const unsigned long long a1 = atomicAdd(&g_acc[1], 0ull);
            const double denom = FIXSCALE * (double)BDIM * (double)KSEL;
            out[0] = (float)((double)a0 / denom);
            out[1] = (float)((double)a1 / denom);
        }
    }
}

// ---------------------------------------------------------------------------
extern "C" void kernel_launch(void* const* d_in, const int* in_sizes, int n_in,
                              void* d_out, int out_size) {
    const float* X = (const float*)d_in[0];
    const float* Y = (const float*)d_in[1];
    float* out = (float*)d_out;

    cudaFuncSetAttribute(gemm_mma_kernel, cudaFuncAttributeMaxDynamicSharedMemorySize,
                         GEMM_SMEM);

    norms_kernel<<<dim3(BDIM, 2), 256>>>(X, Y);
    gemm_mma_kernel<<<dim3(BDIM / BN, BDIM / BM), 256, GEMM_SMEM>>>();
    select_kernel<<<dim3(BDIM, 2), 256>>>(out);
}